// round 14
// baseline (speedup 1.0000x reference)
#include <cuda_runtime.h>
#include <cuda_bf16.h>
#include <cstdint>

#define T_DIM    168
#define C_DIM    1024
#define NSEQ     168
#define HORIZON  24
#define KPAD     176                 // 11 k-steps of 16
#define KSTEPS   11

#define NBLOCKS    592               // 148 SMs x 4 CTAs
#define NSLOTS     (NBLOCKS * 4)     // 2368 warp slots
#define NTILES     16384             // 256 b x 64 groups of 16 ch
#define TILE7_CUT  2176              // warps [0,2176) own 7 tiles, rest 6

// ---- smem layout ----
// per-warp stage chunk: 16 rows x 80 B (64 B data + 16 B pad) = 1280 B
#define WROW_W      20               // words per padded row
#define WSTAGE_B    1280
#define NBUF        4
#define WREGION_B   (NBUF * WSTAGE_B)          // 5120 per warp
#define BFRAG_OFF   (4 * WREGION_B)            // 20480
#define BFRAG_U32   (2 * KSTEPS * 3 * 64)      // 4224 u32 = 16896 B
#define SBETA_OFF   (BFRAG_OFF + BFRAG_U32 * 4)     // 37376
#define WSPAD_OFF   (SBETA_OFF + HORIZON * 4)       // 37472
#define SMEM_BYTES  (WSPAD_OFF + 280 * 4)           // 38592

// =================== PTX helpers ===================
__device__ __forceinline__ void cp16(uint32_t saddr, const void* gptr) {
    asm volatile("cp.async.cg.shared.global [%0], [%1], 16;"
                 :: "r"(saddr), "l"(gptr));
}
__device__ __forceinline__ void cp_commit() {
    asm volatile("cp.async.commit_group;");
}
template<int N>
__device__ __forceinline__ void cp_wait() {
    asm volatile("cp.async.wait_group %0;" :: "n"(N) : "memory");
}
__device__ __forceinline__ uint32_t cvt2(float hi, float lo) {
    uint32_t r;
    asm("cvt.rn.bf16x2.f32 %0, %1, %2;" : "=r"(r) : "f"(hi), "f"(lo));
    return r;
}
__device__ __forceinline__ void split_pair(float v0, float v1,
                                           uint32_t& hp, uint32_t& lp) {
    hp = cvt2(v1, v0);
    float h1 = __uint_as_float(hp & 0xffff0000u);
    float h0 = __uint_as_float(hp << 16);
    lp = cvt2(v1 - h1, v0 - h0);
}
__device__ __forceinline__ void mma16816(float* c, const uint32_t* a,
                                         const uint32_t* b) {
    asm volatile(
        "mma.sync.aligned.m16n8k16.row.col.f32.bf16.bf16.f32 "
        "{%0,%1,%2,%3}, {%4,%5,%6,%7}, {%8,%9}, {%0,%1,%2,%3};"
        : "+f"(c[0]), "+f"(c[1]), "+f"(c[2]), "+f"(c[3])
        : "r"(a[0]), "r"(a[1]), "r"(a[2]), "r"(a[3]), "r"(b[0]), "r"(b[1]));
}
__device__ __forceinline__ void lds_v2(uint32_t& r0, uint32_t& r1, uint32_t addr) {
    asm volatile("ld.shared.v2.u32 {%0,%1}, [%2];"
                 : "=r"(r0), "=r"(r1) : "r"(addr));
}

// =================== fine-grained warp-tile kernel ===================
// Grid = 592 CTAs x 4 warps = 2368 warp slots. Warp-tile = 16 channels x 1 b
// x full K; warp w statically owns tiles w, w+2368, ... (6 or 7 tiles).
// Phase 0 (once per CTA): AR recursion -> bf16 hi/lo mma fragments in SMEM.
// Phase 1: warp-private 4-deep cp.async pipeline rolling across tiles.
__global__ __launch_bounds__(128, 4)
void ar_mma_kernel(const float* __restrict__ y,
                   const float* __restrict__ w,
                   const float* __restrict__ bias,
                   float* __restrict__ out) {
    extern __shared__ char sm[];
    const int tid   = threadIdx.x;
    const int wid   = tid >> 5;
    const int lane  = tid & 31;
    const int lane4 = lane & 3;
    const int laneg = lane >> 2;
    const uint32_t sb = (uint32_t)__cvta_generic_to_shared((void*)sm);

    uint32_t* bf = (uint32_t*)(sm + BFRAG_OFF);
    float* sbeta = (float*)(sm + SBETA_OFF);
    float* wsp   = (float*)(sm + WSPAD_OFF);     // [280] zero-padded w

    // tile id -> base pointer of its 16-channel slice (64 B rows, stride 4096)
    auto tile_base = [&](int t) -> const char* {
        return (const char*)y + (long long)(t >> 6) * (T_DIM * C_DIM * 4)
                              + (long long)(t & 63) * 64;
    };

    const int gwid   = blockIdx.x * 4 + wid;
    const int ntiles = (gwid < TILE7_CUT) ? 7 : 6;
    const int L      = ntiles * KSTEPS;

    const uint32_t wsb = sb + wid * WREGION_B;

    // per-warp chunk prefetch: 16 rows x 64 B -> padded 80 B smem rows
    auto issue_chunk = [&](const char* gsrc, int buf, int nrows) {
        const uint32_t sdst = wsb + buf * WSTAGE_B;
#pragma unroll
        for (int j = 0; j < 2; ++j) {
            int id  = j * 32 + lane;
            int row = id >> 2;               // 0..15
            int col = (id & 3) << 4;         // 0..48 bytes
            if (row < nrows)
                cp16(sdst + row * 80 + col, gsrc + (long long)row * 4096 + col);
        }
        cp_commit();
    };

    // ---- kick DRAM first: chunks 0,1,2 of this warp's first tile ----
    const char* tb0 = tile_base(gwid);
    issue_chunk(tb0,             0, 16);
    issue_chunk(tb0 + 16 * 4096, 1, 16);
    issue_chunk(tb0 + 32 * 4096, 2, 16);

    // ---- ws_pad[280]: zeros everywhere except w at [23..190] ----
    for (int i = tid; i < 280; i += 128) wsp[i] = 0.f;
    __syncthreads();
    for (int i = tid; i < NSEQ; i += 128) wsp[23 + i] = w[i];
    __syncthreads();

    // ================= phase 0: dual-column recursion -> fragments =========
    float wt[HORIZON];
#pragma unroll
    for (int j = 0; j < HORIZON; ++j) wt[j] = wsp[167 + j];   // w[144+j]

    {
        const int t  = tid;            // column 1: 0..127
        const int t2 = tid + 128;      // column 2: 128..255 (valid < 176)
        const bool wr1 = ((t & 1) == 0);
        const bool wr2 = (t2 < KPAD) && ((t & 1) == 0);
        const int kt1  = t >> 4,  r1 = (t >> 3) & 1,  ln41 = (t & 7) >> 1;
        const int kt2  = t2 >> 4, r2 = (t2 >> 3) & 1, ln42 = (t2 & 7) >> 1;
        float col[HORIZON], col2[HORIZON];
#pragma unroll
        for (int h = 0; h < HORIZON; ++h) {
            float a1 = wsp[23 + t - h];       // guard-free (padded)
            float a2 = wsp[23 + t2 - h];
#pragma unroll
            for (int j = 0; j < h; ++j) {
                a1 += wt[24 - h + j] * col[j];
                a2 += wt[24 - h + j] * col2[j];
            }
            col[h] = a1;  col2[h] = a2;
            float v1 = __shfl_xor_sync(0xffffffffu, a1, 1);
            float v2 = __shfl_xor_sync(0xffffffffu, a2, 1);
            if (wr1) {
                uint32_t hp, lp;
                split_pair(a1, v1, hp, lp);
                int base = (kt1 * 3 + (h >> 3)) * 64 + ((h & 7) * 4 + ln41) * 2 + r1;
                bf[base] = hp;
                bf[KSTEPS * 3 * 64 + base] = lp;
            }
            if (wr2) {
                uint32_t hp, lp;
                split_pair(a2, v2, hp, lp);
                int base = (kt2 * 3 + (h >> 3)) * 64 + ((h & 7) * 4 + ln42) * 2 + r2;
                bf[base] = hp;
                bf[KSTEPS * 3 * 64 + base] = lp;
            }
        }
    }
    if (tid == 127) {
        float bb[HORIZON];
        float bv = __ldg(&bias[0]);
#pragma unroll
        for (int h = 0; h < HORIZON; ++h) {
            float acc = bv;
#pragma unroll
            for (int j = 0; j < h; ++j) acc += wt[24 - h + j] * bb[j];
            bb[h] = acc;
            sbeta[h] = acc;
        }
    }
    __syncthreads();      // the LAST block barrier: fragments + beta visible

    // ================= phase 1: warp-private rolling tile stream ============
    const int t0 = lane4 * 2;

    // rolling prefetch state: next stream chunk = (tile gwid, chunk 3)
    int pt = gwid, pch = 3;
    const char* pg = tb0 + 3 * 16 * 4096;
    int tile = gwid;
    int q = 0;

#pragma unroll 1
    for (int k = 0; k < ntiles; ++k) {
        float acc[3][4];
#pragma unroll
        for (int n = 0; n < 3; ++n)
#pragma unroll
            for (int rr = 0; rr < 4; ++rr) acc[n][rr] = 0.f;

#pragma unroll 1
        for (int kt = 0; kt < KSTEPS; ++kt, ++q) {
            if      (q < L - 2)  { cp_wait<2>(); }
            else if (q == L - 2) { cp_wait<1>(); }
            else                 { cp_wait<0>(); }
            __syncwarp();

            if (q + 3 < L) {
                issue_chunk(pg, (q + 3) & 3, (pch == 10) ? 8 : 16);
                if (++pch == KSTEPS) {
                    pch = 0;
                    pt += NSLOTS;
                    pg = tile_base(pt);        // never dereferenced if pt>=NTILES
                } else {
                    pg += 16 * 4096;
                }
            }

            uint32_t Bh[3][2], Bl[3][2];
#pragma unroll
            for (int nt = 0; nt < 3; ++nt) {
                lds_v2(Bh[nt][0], Bh[nt][1],
                       sb + BFRAG_OFF + (uint32_t)(((0 * KSTEPS + kt) * 3 + nt) * 256 + lane * 8));
                lds_v2(Bl[nt][0], Bl[nt][1],
                       sb + BFRAG_OFF + (uint32_t)(((1 * KSTEPS + kt) * 3 + nt) * 256 + lane * 8));
            }

            const float* p = (const float*)(sm + wid * WREGION_B
                                               + (q & 3) * WSTAGE_B) + laneg;
            const bool full = (kt < KSTEPS - 1);

            float w00 = p[t0 * WROW_W],       w01 = p[(t0 + 1) * WROW_W];
            float w10 = p[t0 * WROW_W + 8],   w11 = p[(t0 + 1) * WROW_W + 8];

            uint32_t Ah[4], Al[4];
            split_pair(w00, w01, Ah[0], Al[0]);
            split_pair(w10, w11, Ah[1], Al[1]);
            if (full) {
                float w02 = p[(t0 + 8) * WROW_W],     w03 = p[(t0 + 9) * WROW_W];
                float w12 = p[(t0 + 8) * WROW_W + 8], w13 = p[(t0 + 9) * WROW_W + 8];
                split_pair(w02, w03, Ah[2], Al[2]);
                split_pair(w12, w13, Ah[3], Al[3]);
            } else {
                Ah[2] = Ah[3] = Al[2] = Al[3] = 0u;   // t >= 168 contributes 0
            }

#pragma unroll
            for (int nt = 0; nt < 3; ++nt) {
                mma16816(acc[nt], Ah, Bh[nt]);        // Ah*Bh
                mma16816(acc[nt], Al, Bh[nt]);        // Al*Bh
                mma16816(acc[nt], Ah, Bl[nt]);        // Ah*Bl
            }
        }

        // ---- per-tile epilogue (per-warp, overlaps in-flight loads) ----
        {
            const int bb = tile >> 6;
            const int c0 = (tile & 63) * 16;
            float* ob = out + (long long)bb * HORIZON * C_DIM + c0;
#pragma unroll
            for (int nt = 0; nt < 3; ++nt) {
                const int h0 = nt * 8 + lane4 * 2;
                const float be0 = sbeta[h0];
                const float be1 = sbeta[h0 + 1];
                ob[(long long)h0 * C_DIM + laneg]           = acc[nt][0] + be0;
                ob[(long long)(h0 + 1) * C_DIM + laneg]     = acc[nt][1] + be1;
                ob[(long long)h0 * C_DIM + laneg + 8]       = acc[nt][2] + be0;
                ob[(long long)(h0 + 1) * C_DIM + laneg + 8] = acc[nt][3] + be1;
            }
        }
        tile += NSLOTS;
    }
}

extern "C" void kernel_launch(void* const* d_in, const int* in_sizes, int n_in,
                              void* d_out, int out_size) {
    // metadata order: x (unused), y, w, b
    const float* y    = (const float*)d_in[1];
    const float* w    = (const float*)d_in[2];
    const float* bias = (const float*)d_in[3];
    float* out        = (float*)d_out;

    ar_mma_kernel<<<NBLOCKS, 128, SMEM_BYTES>>>(y, w, bias, out);
}

// round 15
// speedup vs baseline: 1.0167x; 1.0167x over previous
#include <cuda_runtime.h>
#include <cuda_bf16.h>
#include <cstdint>

#define T_DIM    168
#define C_DIM    1024
#define NSEQ     168
#define HORIZON  24
#define KPAD     176                 // 11 k-steps of 16
#define KSTEPS   11

#define NBLOCKS    592               // 148 SMs x 4 CTAs
#define NSLOTS     (NBLOCKS * 4)     // 2368 warp slots
#define NTILES     8192              // 256 b x 32 groups of 32 ch
#define TILE4_CUT  1088              // warps [0,1088) own 4 tiles, rest 3

// ---- smem layout ----
// per-warp stage chunk: 16 rows x 144 B (128 B data + 16 B pad) = 2304 B
#define WROW_W      36               // words per padded row
#define WSTAGE_B    2304
#define NBUF        4
#define WREGION_B   (NBUF * WSTAGE_B)          // 9216 per warp
#define BFRAG_OFF   (4 * WREGION_B)            // 36864
#define BFRAG_U32   (2 * KSTEPS * 3 * 64)      // 4224 u32 = 16896 B
#define SBETA_OFF   (BFRAG_OFF + BFRAG_U32 * 4)     // 53760
#define WSPAD_OFF   (SBETA_OFF + HORIZON * 4)       // 53856
#define SMEM_BYTES  (WSPAD_OFF + 280 * 4)           // 54976

// =================== PTX helpers ===================
__device__ __forceinline__ void cp16(uint32_t saddr, const void* gptr) {
    asm volatile("cp.async.cg.shared.global [%0], [%1], 16;"
                 :: "r"(saddr), "l"(gptr));
}
__device__ __forceinline__ void cp_commit() {
    asm volatile("cp.async.commit_group;");
}
template<int N>
__device__ __forceinline__ void cp_wait() {
    asm volatile("cp.async.wait_group %0;" :: "n"(N) : "memory");
}
__device__ __forceinline__ uint32_t cvt2(float hi, float lo) {
    uint32_t r;
    asm("cvt.rn.bf16x2.f32 %0, %1, %2;" : "=r"(r) : "f"(hi), "f"(lo));
    return r;
}
__device__ __forceinline__ void split_pair(float v0, float v1,
                                           uint32_t& hp, uint32_t& lp) {
    hp = cvt2(v1, v0);
    float h1 = __uint_as_float(hp & 0xffff0000u);
    float h0 = __uint_as_float(hp << 16);
    lp = cvt2(v1 - h1, v0 - h0);
}
__device__ __forceinline__ void mma16816(float* c, const uint32_t* a,
                                         const uint32_t* b) {
    asm volatile(
        "mma.sync.aligned.m16n8k16.row.col.f32.bf16.bf16.f32 "
        "{%0,%1,%2,%3}, {%4,%5,%6,%7}, {%8,%9}, {%0,%1,%2,%3};"
        : "+f"(c[0]), "+f"(c[1]), "+f"(c[2]), "+f"(c[3])
        : "r"(a[0]), "r"(a[1]), "r"(a[2]), "r"(a[3]), "r"(b[0]), "r"(b[1]));
}
__device__ __forceinline__ void lds_v2(uint32_t& r0, uint32_t& r1, uint32_t addr) {
    asm volatile("ld.shared.v2.u32 {%0,%1}, [%2];"
                 : "=r"(r0), "=r"(r1) : "r"(addr));
}

// =================== b-fine warp-tile kernel ===================
// Grid = 592 CTAs x 4 warps = 2368 warp slots. Warp-tile = 32 channels x 1 b
// x full K (11 chunks); warp w statically owns tiles w, w+2368, ... (3 or 4).
// Per-SM chunk totals balanced to ~1.2%. Phase 0 (once per CTA): AR recursion
// -> bf16 hi/lo mma fragments in SMEM. Phase 1: warp-private 4-deep cp.async
// pipeline rolling across tile boundaries.
__global__ __launch_bounds__(128, 4)
void ar_mma_kernel(const float* __restrict__ y,
                   const float* __restrict__ w,
                   const float* __restrict__ bias,
                   float* __restrict__ out) {
    extern __shared__ char sm[];
    const int tid   = threadIdx.x;
    const int wid   = tid >> 5;
    const int lane  = tid & 31;
    const int lane4 = lane & 3;
    const int laneg = lane >> 2;
    const uint32_t sb = (uint32_t)__cvta_generic_to_shared((void*)sm);

    uint32_t* bf = (uint32_t*)(sm + BFRAG_OFF);
    float* sbeta = (float*)(sm + SBETA_OFF);
    float* wsp   = (float*)(sm + WSPAD_OFF);     // [280] zero-padded w

    // tile id -> base pointer of its 32-channel slice (128 B rows, stride 4 KB)
    auto tile_base = [&](int t) -> const char* {
        return (const char*)y + (long long)(t >> 5) * (T_DIM * C_DIM * 4)
                              + (long long)(t & 31) * 128;
    };

    const int gwid   = blockIdx.x * 4 + wid;
    const int ntiles = (gwid < TILE4_CUT) ? 4 : 3;
    const int L      = ntiles * KSTEPS;

    const uint32_t wsb = sb + wid * WREGION_B;

    // per-warp chunk prefetch: 16 rows x 128 B -> padded 144 B smem rows
    auto issue_chunk = [&](const char* gsrc, int buf, int nrows) {
        const uint32_t sdst = wsb + buf * WSTAGE_B;
#pragma unroll
        for (int j = 0; j < 4; ++j) {
            int id  = j * 32 + lane;
            int row = id >> 3;               // 0..15
            int col = (id & 7) << 4;         // 0..112 bytes
            if (row < nrows)
                cp16(sdst + row * 144 + col, gsrc + (long long)row * 4096 + col);
        }
        cp_commit();
    };

    // ---- kick DRAM first: chunks 0,1,2 of this warp's first tile ----
    const char* tb0 = tile_base(gwid);
    issue_chunk(tb0,             0, 16);
    issue_chunk(tb0 + 16 * 4096, 1, 16);
    issue_chunk(tb0 + 32 * 4096, 2, 16);

    // ---- ws_pad[280]: zeros everywhere except w at [23..190] ----
    for (int i = tid; i < 280; i += 128) wsp[i] = 0.f;
    __syncthreads();
    for (int i = tid; i < NSEQ; i += 128) wsp[23 + i] = w[i];
    __syncthreads();

    // ================= phase 0: dual-column recursion -> fragments =========
    float wt[HORIZON];
#pragma unroll
    for (int j = 0; j < HORIZON; ++j) wt[j] = wsp[167 + j];   // w[144+j]

    {
        const int t  = tid;            // column 1: 0..127
        const int t2 = tid + 128;      // column 2: 128..255 (valid < 176)
        const bool wr1 = ((t & 1) == 0);
        const bool wr2 = (t2 < KPAD) && ((t & 1) == 0);
        const int kt1  = t >> 4,  r1 = (t >> 3) & 1,  ln41 = (t & 7) >> 1;
        const int kt2  = t2 >> 4, r2 = (t2 >> 3) & 1, ln42 = (t2 & 7) >> 1;
        float col[HORIZON], col2[HORIZON];
#pragma unroll
        for (int h = 0; h < HORIZON; ++h) {
            float a1 = wsp[23 + t - h];       // guard-free (padded)
            float a2 = wsp[23 + t2 - h];
#pragma unroll
            for (int j = 0; j < h; ++j) {
                a1 += wt[24 - h + j] * col[j];
                a2 += wt[24 - h + j] * col2[j];
            }
            col[h] = a1;  col2[h] = a2;
            float v1 = __shfl_xor_sync(0xffffffffu, a1, 1);
            float v2 = __shfl_xor_sync(0xffffffffu, a2, 1);
            if (wr1) {
                uint32_t hp, lp;
                split_pair(a1, v1, hp, lp);
                int base = (kt1 * 3 + (h >> 3)) * 64 + ((h & 7) * 4 + ln41) * 2 + r1;
                bf[base] = hp;
                bf[KSTEPS * 3 * 64 + base] = lp;
            }
            if (wr2) {
                uint32_t hp, lp;
                split_pair(a2, v2, hp, lp);
                int base = (kt2 * 3 + (h >> 3)) * 64 + ((h & 7) * 4 + ln42) * 2 + r2;
                bf[base] = hp;
                bf[KSTEPS * 3 * 64 + base] = lp;
            }
        }
    }
    if (tid == 127) {
        float bb[HORIZON];
        float bv = __ldg(&bias[0]);
#pragma unroll
        for (int h = 0; h < HORIZON; ++h) {
            float acc = bv;
#pragma unroll
            for (int j = 0; j < h; ++j) acc += wt[24 - h + j] * bb[j];
            bb[h] = acc;
            sbeta[h] = acc;
        }
    }
    __syncthreads();      // the LAST block barrier: fragments + beta visible

    // ================= phase 1: warp-private rolling tile stream ============
    const int t0 = lane4 * 2;

    // rolling prefetch state: next stream chunk = (tile gwid, chunk 3)
    int pt = gwid, pch = 3;
    const char* pg = tb0 + 3 * 16 * 4096;
    int tile = gwid;
    int q = 0;

#pragma unroll 1
    for (int k = 0; k < ntiles; ++k) {
        float acc[2][3][4];
#pragma unroll
        for (int m = 0; m < 2; ++m)
#pragma unroll
            for (int n = 0; n < 3; ++n)
#pragma unroll
                for (int rr = 0; rr < 4; ++rr) acc[m][n][rr] = 0.f;

#pragma unroll 1
        for (int kt = 0; kt < KSTEPS; ++kt, ++q) {
            if      (q < L - 2)  { cp_wait<2>(); }
            else if (q == L - 2) { cp_wait<1>(); }
            else                 { cp_wait<0>(); }
            __syncwarp();

            if (q + 3 < L) {
                issue_chunk(pg, (q + 3) & 3, (pch == 10) ? 8 : 16);
                if (++pch == KSTEPS) {
                    pch = 0;
                    pt += NSLOTS;
                    pg = tile_base(pt);        // never dereferenced if pt>=NTILES
                } else {
                    pg += 16 * 4096;
                }
            }

            uint32_t Bh[3][2], Bl[3][2];
#pragma unroll
            for (int nt = 0; nt < 3; ++nt) {
                lds_v2(Bh[nt][0], Bh[nt][1],
                       sb + BFRAG_OFF + (uint32_t)(((0 * KSTEPS + kt) * 3 + nt) * 256 + lane * 8));
                lds_v2(Bl[nt][0], Bl[nt][1],
                       sb + BFRAG_OFF + (uint32_t)(((1 * KSTEPS + kt) * 3 + nt) * 256 + lane * 8));
            }

            const float* pw = (const float*)(sm + wid * WREGION_B
                                                + (q & 3) * WSTAGE_B);
            const bool full = (kt < KSTEPS - 1);

#pragma unroll
            for (int m = 0; m < 2; ++m) {
                const float* p = pw + m * 16 + laneg;   // [t][ch]: stride 36 words

                float w00 = p[t0 * WROW_W],       w01 = p[(t0 + 1) * WROW_W];
                float w10 = p[t0 * WROW_W + 8],   w11 = p[(t0 + 1) * WROW_W + 8];

                uint32_t Ah[4], Al[4];
                split_pair(w00, w01, Ah[0], Al[0]);
                split_pair(w10, w11, Ah[1], Al[1]);
                if (full) {
                    float w02 = p[(t0 + 8) * WROW_W],     w03 = p[(t0 + 9) * WROW_W];
                    float w12 = p[(t0 + 8) * WROW_W + 8], w13 = p[(t0 + 9) * WROW_W + 8];
                    split_pair(w02, w03, Ah[2], Al[2]);
                    split_pair(w12, w13, Ah[3], Al[3]);
                } else {
                    Ah[2] = Ah[3] = Al[2] = Al[3] = 0u;   // t >= 168 contributes 0
                }

#pragma unroll
                for (int nt = 0; nt < 3; ++nt) {
                    mma16816(acc[m][nt], Ah, Bh[nt]);     // Ah*Bh
                    mma16816(acc[m][nt], Al, Bh[nt]);     // Al*Bh
                    mma16816(acc[m][nt], Ah, Bl[nt]);     // Ah*Bl
                }
            }
        }

        // ---- per-tile epilogue (per-warp, overlaps in-flight loads) ----
        {
            const int bb = tile >> 5;
            const int c0 = (tile & 31) * 32;
            float* ob = out + (long long)bb * HORIZON * C_DIM + c0;
#pragma unroll
            for (int nt = 0; nt < 3; ++nt) {
                const int h0 = nt * 8 + lane4 * 2;
                const float be0 = sbeta[h0];
                const float be1 = sbeta[h0 + 1];
#pragma unroll
                for (int m = 0; m < 2; ++m) {
                    const int row = m * 16 + laneg;
                    ob[(long long)h0 * C_DIM + row]           = acc[m][nt][0] + be0;
                    ob[(long long)(h0 + 1) * C_DIM + row]     = acc[m][nt][1] + be1;
                    ob[(long long)h0 * C_DIM + row + 8]       = acc[m][nt][2] + be0;
                    ob[(long long)(h0 + 1) * C_DIM + row + 8] = acc[m][nt][3] + be1;
                }
            }
        }
        tile += NSLOTS;
    }
}

extern "C" void kernel_launch(void* const* d_in, const int* in_sizes, int n_in,
                              void* d_out, int out_size) {
    // metadata order: x (unused), y, w, b
    const float* y    = (const float*)d_in[1];
    const float* w    = (const float*)d_in[2];
    const float* bias = (const float*)d_in[3];
    float* out        = (float*)d_out;

    static bool attr_set = false;
    if (!attr_set) {
        cudaFuncSetAttribute(ar_mma_kernel,
                             cudaFuncAttributeMaxDynamicSharedMemorySize,
                             SMEM_BYTES);
        attr_set = true;
    }

    ar_mma_kernel<<<NBLOCKS, 128, SMEM_BYTES>>>(y, w, bias, out);
}

// round 16
// speedup vs baseline: 1.0394x; 1.0223x over previous
#include <cuda_runtime.h>
#include <cuda_bf16.h>
#include <cstdint>

#define T_DIM    168
#define C_DIM    1024
#define NSEQ     168
#define HORIZON  24
#define KPAD     176                 // 11 k-steps of 16
#define KSTEPS   11

#define NBLOCKS    740               // 148 SMs x 5 CTAs (one full wave)
#define NSLOTS     (NBLOCKS * 4)     // 2960 warp slots
#define NTILES     8192              // 256 b x 32 groups of 32 ch
#define NEXTRA     (NTILES - 2 * NSLOTS)   // 2272 third-tiles (Bresenham spread)

// ---- smem layout ----
// per-warp stage chunk: 16 rows x 144 B (128 B data + 16 B pad) = 2304 B
#define WROW_W      36               // words per padded row
#define WSTAGE_B    2304
#define NBUF        3
#define WREGION_B   (NBUF * WSTAGE_B)          // 6912 per warp
#define BFRAG_OFF   (4 * WREGION_B)            // 27648
#define BFRAG_U32   (2 * KSTEPS * 3 * 64)      // 4224 u32 = 16896 B
#define SBETA_OFF   (BFRAG_OFF + BFRAG_U32 * 4)     // 44544
#define SMEM_BYTES  (SBETA_OFF + HORIZON * 4)       // 44640 (< 48K, 5 CTAs/SM)
#define WSPAD_OFF   (2 * WSTAGE_B)   // transient [280] fp32 overlaid in warp0
                                     // buffer 2 (first cp.async write: chunk 2,
                                     // issued after the phase-0 barrier)

// =================== PTX helpers ===================
__device__ __forceinline__ void cp16(uint32_t saddr, const void* gptr) {
    asm volatile("cp.async.cg.shared.global [%0], [%1], 16;"
                 :: "r"(saddr), "l"(gptr));
}
__device__ __forceinline__ void cp_commit() {
    asm volatile("cp.async.commit_group;");
}
template<int N>
__device__ __forceinline__ void cp_wait() {
    asm volatile("cp.async.wait_group %0;" :: "n"(N) : "memory");
}
__device__ __forceinline__ uint32_t cvt2(float hi, float lo) {
    uint32_t r;
    asm("cvt.rn.bf16x2.f32 %0, %1, %2;" : "=r"(r) : "f"(hi), "f"(lo));
    return r;
}
__device__ __forceinline__ void split_pair(float v0, float v1,
                                           uint32_t& hp, uint32_t& lp) {
    hp = cvt2(v1, v0);
    float h1 = __uint_as_float(hp & 0xffff0000u);
    float h0 = __uint_as_float(hp << 16);
    lp = cvt2(v1 - h1, v0 - h0);
}
__device__ __forceinline__ void mma16816(float* c, const uint32_t* a,
                                         const uint32_t* b) {
    asm volatile(
        "mma.sync.aligned.m16n8k16.row.col.f32.bf16.bf16.f32 "
        "{%0,%1,%2,%3}, {%4,%5,%6,%7}, {%8,%9}, {%0,%1,%2,%3};"
        : "+f"(c[0]), "+f"(c[1]), "+f"(c[2]), "+f"(c[3])
        : "r"(a[0]), "r"(a[1]), "r"(a[2]), "r"(a[3]), "r"(b[0]), "r"(b[1]));
}
__device__ __forceinline__ void lds_v2(uint32_t& r0, uint32_t& r1, uint32_t addr) {
    asm volatile("ld.shared.v2.u32 {%0,%1}, [%2];"
                 : "=r"(r0), "=r"(r1) : "r"(addr));
}

// =================== 5-CTA/SM warp-tile kernel ===================
// Grid = 740 CTAs x 4 warps = 2960 warp slots, 20 warps/SM. Warp-tile = 32
// channels x 1 b x full K (11 chunks). Every warp owns 2 base tiles
// (gwid, gwid+2960); 2272 extra tiles are spread Bresenham-uniformly.
// Phase 0 (once per CTA): AR recursion -> bf16 hi/lo mma fragments in SMEM.
// Phase 1: warp-private depth-2 cp.async pipeline rolling across tiles.
__global__ __launch_bounds__(128, 5)
void ar_mma_kernel(const float* __restrict__ y,
                   const float* __restrict__ w,
                   const float* __restrict__ bias,
                   float* __restrict__ out) {
    extern __shared__ char sm[];
    const int tid   = threadIdx.x;
    const int wid   = tid >> 5;
    const int lane  = tid & 31;
    const int lane4 = lane & 3;
    const int laneg = lane >> 2;
    const uint32_t sb = (uint32_t)__cvta_generic_to_shared((void*)sm);

    uint32_t* bf = (uint32_t*)(sm + BFRAG_OFF);
    float* sbeta = (float*)(sm + SBETA_OFF);
    float* wsp   = (float*)(sm + WSPAD_OFF);     // [280], overlay in warp0 buf2

    // tile id -> base pointer of its 32-channel slice (128 B rows, stride 4 KB)
    auto tile_base = [&](int t) -> const char* {
        return (const char*)y + (long long)(t >> 5) * (T_DIM * C_DIM * 4)
                              + (long long)(t & 31) * 128;
    };

    const int gwid  = blockIdx.x * 4 + wid;
    // Bresenham spread of the 2272 extra tiles across 2960 warps
    const int hrank  = (int)(((unsigned)gwid * NEXTRA) / NSLOTS);
    const int hnext  = (int)(((unsigned)(gwid + 1) * NEXTRA) / NSLOTS);
    const int heavy  = hnext - hrank;            // 0 or 1
    const int ntiles = 2 + heavy;
    const int L      = ntiles * KSTEPS;
    const int tile3  = 2 * NSLOTS + hrank;       // valid index even if !heavy

    const uint32_t wsb = sb + wid * WREGION_B;

    // per-warp chunk prefetch: 16 rows x 128 B -> padded 144 B smem rows
    auto issue_chunk = [&](const char* gsrc, int buf, int nrows) {
        const uint32_t sdst = wsb + buf * WSTAGE_B;
#pragma unroll
        for (int j = 0; j < 4; ++j) {
            int id  = j * 32 + lane;
            int row = id >> 3;               // 0..15
            int col = (id & 7) << 4;         // 0..112 bytes
            if (row < nrows)
                cp16(sdst + row * 144 + col, gsrc + (long long)row * 4096 + col);
        }
        cp_commit();
    };

    // ---- kick DRAM first: chunks 0,1 of this warp's first tile ----
    const char* tb0 = tile_base(gwid);
    issue_chunk(tb0,             0, 16);
    issue_chunk(tb0 + 16 * 4096, 1, 16);

    // ---- ws_pad[280]: zeros everywhere except w at [23..190] ----
    for (int i = tid; i < 280; i += 128) wsp[i] = 0.f;
    __syncthreads();
    for (int i = tid; i < NSEQ; i += 128) wsp[23 + i] = w[i];
    __syncthreads();

    // ================= phase 0: dual-column recursion -> fragments =========
    float wt[HORIZON];
#pragma unroll
    for (int j = 0; j < HORIZON; ++j) wt[j] = wsp[167 + j];   // w[144+j]

    {
        const int t  = tid;            // column 1: 0..127
        const int t2 = tid + 128;      // column 2: 128..255 (valid < 176)
        const bool wr1 = ((t & 1) == 0);
        const bool wr2 = (t2 < KPAD) && ((t & 1) == 0);
        const int kt1  = t >> 4,  r1 = (t >> 3) & 1,  ln41 = (t & 7) >> 1;
        const int kt2  = t2 >> 4, r2 = (t2 >> 3) & 1, ln42 = (t2 & 7) >> 1;
        float col[HORIZON], col2[HORIZON];
#pragma unroll
        for (int h = 0; h < HORIZON; ++h) {
            float a1 = wsp[23 + t - h];       // guard-free (padded)
            float a2 = wsp[23 + t2 - h];
#pragma unroll
            for (int j = 0; j < h; ++j) {
                a1 += wt[24 - h + j] * col[j];
                a2 += wt[24 - h + j] * col2[j];
            }
            col[h] = a1;  col2[h] = a2;
            float v1 = __shfl_xor_sync(0xffffffffu, a1, 1);
            float v2 = __shfl_xor_sync(0xffffffffu, a2, 1);
            if (wr1) {
                uint32_t hp, lp;
                split_pair(a1, v1, hp, lp);
                int base = (kt1 * 3 + (h >> 3)) * 64 + ((h & 7) * 4 + ln41) * 2 + r1;
                bf[base] = hp;
                bf[KSTEPS * 3 * 64 + base] = lp;
            }
            if (wr2) {
                uint32_t hp, lp;
                split_pair(a2, v2, hp, lp);
                int base = (kt2 * 3 + (h >> 3)) * 64 + ((h & 7) * 4 + ln42) * 2 + r2;
                bf[base] = hp;
                bf[KSTEPS * 3 * 64 + base] = lp;
            }
        }
    }
    if (tid == 127) {
        float bb[HORIZON];
        float bv = __ldg(&bias[0]);
#pragma unroll
        for (int h = 0; h < HORIZON; ++h) {
            float acc = bv;
#pragma unroll
            for (int j = 0; j < h; ++j) acc += wt[24 - h + j] * bb[j];
            bb[h] = acc;
            sbeta[h] = acc;
        }
    }
    __syncthreads();      // last block barrier: fragments + beta visible;
                          // wsp overlay dead (chunk 2 writes it after this)

    // ================= phase 1: warp-private rolling tile stream ============
    const int t0 = lane4 * 2;

    // rolling prefetch state: next stream chunk = (tile gwid, chunk 2)
    int pt = gwid, pch = 2, pbuf = 2;
    const char* pg = tb0 + 2 * 16 * 4096;
    int tile = gwid;
    int cbuf = 0;
    int q = 0;

#pragma unroll 1
    for (int k = 0; k < ntiles; ++k) {
        float acc[2][3][4];
#pragma unroll
        for (int m = 0; m < 2; ++m)
#pragma unroll
            for (int n = 0; n < 3; ++n)
#pragma unroll
                for (int rr = 0; rr < 4; ++rr) acc[m][n][rr] = 0.f;

#pragma unroll 1
        for (int kt = 0; kt < KSTEPS; ++kt, ++q) {
            if (q < L - 1) { cp_wait<1>(); } else { cp_wait<0>(); }
            __syncwarp();

            if (q + 2 < L) {
                issue_chunk(pg, pbuf, (pch == 10) ? 8 : 16);
                pbuf = (pbuf == 2) ? 0 : pbuf + 1;
                if (++pch == KSTEPS) {
                    pch = 0;
                    pt = (pt == gwid) ? gwid + NSLOTS : tile3;
                    pg = tile_base(pt);        // never consumed beyond L
                } else {
                    pg += 16 * 4096;
                }
            }

            uint32_t Bh[3][2], Bl[3][2];
#pragma unroll
            for (int nt = 0; nt < 3; ++nt) {
                lds_v2(Bh[nt][0], Bh[nt][1],
                       sb + BFRAG_OFF + (uint32_t)(((0 * KSTEPS + kt) * 3 + nt) * 256 + lane * 8));
                lds_v2(Bl[nt][0], Bl[nt][1],
                       sb + BFRAG_OFF + (uint32_t)(((1 * KSTEPS + kt) * 3 + nt) * 256 + lane * 8));
            }

            const float* pw = (const float*)(sm + wid * WREGION_B
                                                + cbuf * WSTAGE_B);
            cbuf = (cbuf == 2) ? 0 : cbuf + 1;
            const bool full = (kt < KSTEPS - 1);

#pragma unroll
            for (int m = 0; m < 2; ++m) {
                const float* p = pw + m * 16 + laneg;   // [t][ch]: stride 36 words

                float w00 = p[t0 * WROW_W],       w01 = p[(t0 + 1) * WROW_W];
                float w10 = p[t0 * WROW_W + 8],   w11 = p[(t0 + 1) * WROW_W + 8];

                uint32_t Ah[4], Al[4];
                split_pair(w00, w01, Ah[0], Al[0]);
                split_pair(w10, w11, Ah[1], Al[1]);
                if (full) {
                    float w02 = p[(t0 + 8) * WROW_W],     w03 = p[(t0 + 9) * WROW_W];
                    float w12 = p[(t0 + 8) * WROW_W + 8], w13 = p[(t0 + 9) * WROW_W + 8];
                    split_pair(w02, w03, Ah[2], Al[2]);
                    split_pair(w12, w13, Ah[3], Al[3]);
                } else {
                    Ah[2] = Ah[3] = Al[2] = Al[3] = 0u;   // t >= 168 contributes 0
                }

#pragma unroll
                for (int nt = 0; nt < 3; ++nt) {
                    mma16816(acc[m][nt], Ah, Bh[nt]);     // Ah*Bh
                    mma16816(acc[m][nt], Al, Bh[nt]);     // Al*Bh
                    mma16816(acc[m][nt], Ah, Bl[nt]);     // Ah*Bl
                }
            }
        }

        // ---- per-tile epilogue (per-warp, overlaps in-flight loads) ----
        {
            const int bb = tile >> 5;
            const int c0 = (tile & 31) * 32;
            float* ob = out + (long long)bb * HORIZON * C_DIM + c0;
#pragma unroll
            for (int nt = 0; nt < 3; ++nt) {
                const int h0 = nt * 8 + lane4 * 2;
                const float be0 = sbeta[h0];
                const float be1 = sbeta[h0 + 1];
#pragma unroll
                for (int m = 0; m < 2; ++m) {
                    const int row = m * 16 + laneg;
                    ob[(long long)h0 * C_DIM + row]           = acc[m][nt][0] + be0;
                    ob[(long long)(h0 + 1) * C_DIM + row]     = acc[m][nt][1] + be1;
                    ob[(long long)h0 * C_DIM + row + 8]       = acc[m][nt][2] + be0;
                    ob[(long long)(h0 + 1) * C_DIM + row + 8] = acc[m][nt][3] + be1;
                }
            }
        }
        tile = (tile == gwid) ? gwid + NSLOTS : tile3;
    }
}

extern "C" void kernel_launch(void* const* d_in, const int* in_sizes, int n_in,
                              void* d_out, int out_size) {
    // metadata order: x (unused), y, w, b
    const float* y    = (const float*)d_in[1];
    const float* w    = (const float*)d_in[2];
    const float* bias = (const float*)d_in[3];
    float* out        = (float*)d_out;

    ar_mma_kernel<<<NBLOCKS, 128, SMEM_BYTES>>>(y, w, bias, out);
}